// round 15
// baseline (speedup 1.0000x reference)
#include <cuda_runtime.h>

#define NN 1024
#define EE 2048
#define HID 192
#define KCH 5
#define NL 4
#define NAUG 1152
#define RSA 68
#define SMEM_MAIN ((192*RSA + 2*192*64)*4)         // 150528
#define SMEM_CHEB ((1024 + 16384 + 4096)*4)        // 86016

typedef unsigned long long ull;

// ---------------- device scratch (allocation-free) ----------------
__device__ float g_S[4*NN*4];
__device__ float g_h0[NN*HID];
__device__ float g_h1[NN*HID];
__device__ float g_Y[NN*NAUG];
__device__ float g_B[NL][HID*NAUG];   // [layer][k][n] fp32
__device__ unsigned g_bar;

// ---------------- helpers ----------------
__device__ __forceinline__ void fma2(ull &c, ull a, ull b) {
    asm("fma.rn.f32x2 %0, %1, %2, %0;" : "+l"(c) : "l"(a), "l"(b));
}
__device__ __forceinline__ ull pk2(float a) {
    ull r; asm("mov.b64 %0, {%1, %1};" : "=l"(r) : "f"(a)); return r;
}
__device__ __forceinline__ float2 up2(ull a) {
    float2 f; asm("mov.b64 {%0, %1}, %2;" : "=f"(f.x), "=f"(f.y) : "l"(a)); return f;
}
__device__ __forceinline__ float4 ldcg4(const float4* p) { return __ldcg(p); }
__device__ __forceinline__ void gbar(unsigned target) {
    __threadfence();
    __syncthreads();
    if (threadIdx.x == 0) {
        atomicAdd(&g_bar, 1u);
        while (*((volatile unsigned*)&g_bar) < target) __nanosleep(32);
    }
    __syncthreads();
}

// ---------------- k_M: Mstack fp32 (36x4 blocks) + cheb prep (block 36,0) ----------------
__global__ void __launch_bounds__(256) k_M(const float* __restrict__ nn2_w,
                                           const float* __restrict__ nn2_b,
                                           const float* __restrict__ eenc_w,
                                           const float* __restrict__ eenc_b,
                                           const float* __restrict__ nn1_w,
                                           const float* __restrict__ nn1_b,
                                           const float* __restrict__ root_w,
                                           const int* __restrict__ ei,
                                           const float* __restrict__ x) {
    int t = threadIdx.x;
    if (blockIdx.x == 0 && blockIdx.y == 0 && t == 0) g_bar = 0;   // reset grid barrier
    if (blockIdx.x == 36) {
        if (blockIdx.y != 0) return;
        extern __shared__ float dsm[];
        float* sdeg = dsm;
        float* sS   = dsm + 1024;
        float* sX   = dsm + 1024 + 16384;
        #pragma unroll
        for (int i = 0; i < 4; i++) sdeg[t + 256*i] = 0.f;
        #pragma unroll
        for (int i = 0; i < 64; i++) sS[t + 256*i] = 0.f;
        #pragma unroll
        for (int i = 0; i < 16; i++) sX[t + 256*i] = x[t + 256*i];
        __syncthreads();
        int s[8], d[8]; float w[8];
        #pragma unroll
        for (int j = 0; j < 8; j++) {
            int e = t*8 + j;
            s[j] = ei[e]; d[j] = ei[EE + e];
            atomicAdd(&sdeg[s[j]], 1.f);
        }
        __syncthreads();
        float dv[4];
        #pragma unroll
        for (int i = 0; i < 4; i++) dv[i] = sdeg[t + 256*i];
        __syncthreads();
        #pragma unroll
        for (int i = 0; i < 4; i++) sdeg[t + 256*i] = dv[i] > 0.f ? rsqrtf(dv[i]) : 0.f;
        __syncthreads();
        #pragma unroll
        for (int j = 0; j < 8; j++) w[j] = -sdeg[s[j]] * sdeg[d[j]];
        #pragma unroll
        for (int j = 0; j < 8; j++)
            #pragma unroll
            for (int c = 0; c < 4; c++)
                atomicAdd(&sS[d[j]*4 + c], w[j] * sX[s[j]*4 + c]);
        __syncthreads();
        #pragma unroll
        for (int j = 0; j < 8; j++)
            #pragma unroll
            for (int c = 0; c < 4; c++)
                atomicAdd(&sS[4096 + d[j]*4 + c], w[j] * sS[s[j]*4 + c]);
        __syncthreads();
        #pragma unroll
        for (int j = 0; j < 8; j++)
            #pragma unroll
            for (int c = 0; c < 4; c++)
                atomicAdd(&sS[8192 + d[j]*4 + c],
                          w[j] * (2.f*sS[4096 + s[j]*4 + c] - sX[s[j]*4 + c]));
        __syncthreads();
        #pragma unroll
        for (int j = 0; j < 8; j++)
            #pragma unroll
            for (int c = 0; c < 4; c++)
                atomicAdd(&sS[12288 + d[j]*4 + c],
                          w[j] * (2.f*sS[8192 + s[j]*4 + c] - sS[s[j]*4 + c]));
        __syncthreads();
        #pragma unroll
        for (int i = 0; i < 64; i++) g_S[t + 256*i] = sS[t + 256*i];
        return;
    }

    int i = blockIdx.y;
    __shared__ float2 sG[5*HID];
    if (t < HID) {
        float acc5[5] = {0.f, 0.f, 0.f, 0.f, 0.f};
        const float* W1 = nn1_w + i*HID*HID;
        for (int jb = 0; jb < HID; jb += 8) {
            float wv[8];
            #pragma unroll
            for (int u = 0; u < 8; u++) wv[u] = __ldg(W1 + (jb + u)*HID + t);
            #pragma unroll
            for (int u = 0; u < 8; u++) {
                int j0 = jb + u;
                acc5[0] += eenc_w[j0]*wv[u];
                acc5[1] += eenc_w[HID + j0]*wv[u];
                acc5[2] += eenc_w[2*HID + j0]*wv[u];
                acc5[3] += eenc_w[3*HID + j0]*wv[u];
                acc5[4] += eenc_b[j0]*wv[u];
            }
        }
        acc5[4] += nn1_b[i*HID + t];
        #pragma unroll
        for (int k = 0; k < 5; k++) sG[k*HID + t] = make_float2(acc5[k], acc5[k]);
    }
    {
        int m = blockIdx.x*1024 + t*4;
        int j = m / HID, o = m - j*HID;
        float4 v = *(const float4*)(root_w + (size_t)i*HID*HID + m);
        *(float4*)(g_B[i] + j*NAUG + 5*HID + o) = v;
    }
    __syncthreads();

    int m4 = (blockIdx.x*256 + t) * 4;
    const float* W = nn2_w + (size_t)i * HID * (HID*HID);
    ull acc[5][2] = {};
    for (int jb = 0; jb < HID; jb += 8) {
        float4 vv[8];
        #pragma unroll
        for (int u = 0; u < 8; u++)
            vv[u] = __ldg((const float4*)(W + (size_t)(jb + u)*(HID*HID) + m4));
        #pragma unroll
        for (int u = 0; u < 8; u++) {
            int j = jb + u;
            ull v01, v23;
            asm("mov.b64 %0, {%1, %2};" : "=l"(v01) : "f"(vv[u].x), "f"(vv[u].y));
            asm("mov.b64 %0, {%1, %2};" : "=l"(v23) : "f"(vv[u].z), "f"(vv[u].w));
            #pragma unroll
            for (int k = 0; k < 5; k++) {
                ull gk = *(const ull*)&sG[k*HID + j];
                fma2(acc[k][0], gk, v01);
                fma2(acc[k][1], gk, v23);
            }
        }
    }
    float4 b = __ldg((const float4*)(nn2_b + (size_t)i*(HID*HID) + m4));
    float2 a40 = up2(acc[4][0]), a41 = up2(acc[4][1]);
    a40.x += b.x; a40.y += b.y; a41.x += b.z; a41.y += b.w;
    int j2 = m4 / HID;
    int o  = m4 - j2 * HID;
    float* dst = g_B[i] + j2*NAUG + o;
    #pragma unroll
    for (int k = 0; k < 4; k++) {
        *(float2*)(dst + k*HID)     = up2(acc[k][0]);
        *(float2*)(dst + k*HID + 2) = up2(acc[k][1]);
    }
    *(float2*)(dst + 4*HID)     = a40;
    *(float2*)(dst + 4*HID + 2) = a41;
}

// ---------------- persistent main kernel ----------------
__global__ void __launch_bounds__(512, 1)
k_main(const float* __restrict__ x, const int* __restrict__ ei,
       const float* __restrict__ attr,
       const float* __restrict__ cw, const float* __restrict__ cbb,
       const float* __restrict__ conv_b,
       const float* __restrict__ lng, const float* __restrict__ lnb,
       const float* __restrict__ ow, const float* __restrict__ ob,
       float* __restrict__ out) {
    extern __shared__ float sm[];
    float* sA  = sm;                 // [192][RSA] non-dup, [k][m]
    float* sB0 = sm + 192*RSA;       // [192][64]
    float* sB1 = sB0 + 192*64;
    int t = threadIdx.x, b = blockIdx.x;
    int m0  = (b & 15) * 64;
    int njA = b >> 4;                // 0..8 ; partner n-tile njA+9

    // ---- phase: cheb_out (t<384) + B-prefetch layer0 (t>=384) ----
    if (t < 384) {
        int g = t / 192, o = t - g*192;
        for (int i = 0; i < 4; i++) {
            int r = b*2 + g + 288*i;
            if (r < NN) {
                float acc = __ldg(cbb + o);
                #pragma unroll
                for (int c = 0; c < 4; c++) {
                    float xv = __ldg(x + r*4 + c);
                    float s1 = g_S[r*4+c],        s2 = g_S[4096 + r*4+c];
                    float s3 = g_S[8192 + r*4+c], s4 = g_S[12288 + r*4+c];
                    float t2 = 2.f*s2 - xv, t3 = 2.f*s3 - s1, t4 = 2.f*s4 - 2.f*s2 + xv;
                    acc += xv*__ldg(cw + c*HID + o)
                         + s1*__ldg(cw + (4+c)*HID + o)
                         + t2*__ldg(cw + (8+c)*HID + o)
                         + t3*__ldg(cw + (12+c)*HID + o)
                         + t4*__ldg(cw + (16+c)*HID + o);
                }
                g_h0[r*HID + o] = acc;
            }
        }
    } else {
        int li = t - 384;
        const float* Bm = g_B[0];
        #pragma unroll 4
        for (int i = 0; i < 48; i++) {
            int f = li + 128*i;
            int tile = f / 3072, r = f - tile*3072;
            int kk = r >> 4, w4 = r & 15;
            int nj = tile ? (njA + 9) : njA;
            float4 v = __ldg((const float4*)(Bm + kk*NAUG + nj*64 + w4*4));
            *(float4*)((tile ? sB1 : sB0) + kk*64 + w4*4) = v;
        }
    }
    gbar(144u);

    for (int L = 0; L < NL; L++) {
        const float* hin  = (L & 1) ? g_h1 : g_h0;
        float*       hout = (L & 1) ? g_h0 : g_h1;
        int do_ln = (L > 0);

        // ---- A prologue: 64 rows x 4 threads/row (t < 256), LN in registers ----
        if (t < 256) {
            int m = t >> 2, q = t & 3;
            const float4* rp = (const float4*)(hin + (size_t)(m0 + m)*HID) + q*12;
            float4 v[12];
            #pragma unroll
            for (int i = 0; i < 12; i++) v[i] = ldcg4(rp + i);
            float mu = 0.f, rs = 0.f;
            if (do_ln) {
                float s = 0.f, qq = 0.f;
                #pragma unroll
                for (int i = 0; i < 12; i++) {
                    s  += (v[i].x + v[i].y) + (v[i].z + v[i].w);
                    qq += v[i].x*v[i].x + v[i].y*v[i].y + v[i].z*v[i].z + v[i].w*v[i].w;
                }
                s  += __shfl_xor_sync(0xffffffffu, s, 1);
                s  += __shfl_xor_sync(0xffffffffu, s, 2);
                qq += __shfl_xor_sync(0xffffffffu, qq, 1);
                qq += __shfl_xor_sync(0xffffffffu, qq, 2);
                mu = s * (1.f/192.f);
                rs = rsqrtf(qq*(1.f/192.f) - mu*mu + 1e-5f);
            }
            #pragma unroll
            for (int i = 0; i < 12; i++) {
                int k = q*48 + i*4;
                float vv[4] = {v[i].x, v[i].y, v[i].z, v[i].w};
                #pragma unroll
                for (int e = 0; e < 4; e++) {
                    float z = vv[e];
                    if (do_ln)
                        z = fmaxf(0.f, (z - mu)*rs*__ldg(lng + L*HID + k + e)
                                        + __ldg(lnb + L*HID + k + e));
                    sA[(k + e)*RSA + m] = z;
                }
            }
        }
        __syncthreads();

        // ---- GEMM main: warp-uniform A broadcast; lane = 8m x 2n ----
        {
            int half = t >> 8, th = t & 255;
            int w = th >> 5, lane = th & 31;       // warp m-offset 8*w
            const float* sB = half ? sB1 : sB0;
            int nj = half ? (njA + 9) : njA;
            const float* aBase = sA + 8*w;
            const float* bBase = sB + 2*lane;
            ull acc[8] = {};
            #pragma unroll 4
            for (int kk = 0; kk < 192; kk++) {
                float4 a0 = *(const float4*)(aBase + kk*RSA);
                float4 a1 = *(const float4*)(aBase + kk*RSA + 4);
                ull bp = *(const ull*)(bBase + kk*64);
                fma2(acc[0], pk2(a0.x), bp);
                fma2(acc[1], pk2(a0.y), bp);
                fma2(acc[2], pk2(a0.z), bp);
                fma2(acc[3], pk2(a0.w), bp);
                fma2(acc[4], pk2(a1.x), bp);
                fma2(acc[5], pk2(a1.y), bp);
                fma2(acc[6], pk2(a1.z), bp);
                fma2(acc[7], pk2(a1.w), bp);
            }
            int n0 = nj*64;
            int nc = 2*lane;
            if (nj < 15) {
                #pragma unroll
                for (int i = 0; i < 8; i++)
                    *(float2*)(g_Y + (size_t)(m0 + 8*w + i)*NAUG + n0 + nc) = up2(acc[i]);
            } else {
                int ob2 = n0 - 960 + nc;
                float2 cbv = *(const float2*)(conv_b + L*HID + ob2);
                #pragma unroll
                for (int i = 0; i < 8; i++) {
                    int row = m0 + 8*w + i;
                    float2 r = up2(acc[i]);
                    r.x += cbv.x; r.y += cbv.y;
                    if (do_ln) {
                        float2 hv = __ldcg((const float2*)(hin + (size_t)row*HID + ob2));
                        r.x += hv.x; r.y += hv.y;
                    }
                    *(float2*)(hout + (size_t)row*HID + ob2) = r;
                }
            }
        }
        gbar(144u*(2 + 2*L));

        // ---- escatter (t<384) + B-prefetch layer L+1 (t>=384) ----
        if (t < 384) {
            int g = t / 48, o4 = t - g*48;
            #pragma unroll
            for (int i = 0; i < 2; i++) {
                int e = b*8 + g + 1152*i;
                if (e < EE) {
                    int s = __ldg(ei + e), d = __ldg(ei + EE + e);
                    float4 a = __ldg((const float4*)(attr + e*4));
                    const float4* Ys = (const float4*)(g_Y + (size_t)s*NAUG);
                    float4 y0 = ldcg4(Ys + o4),       y1 = ldcg4(Ys + 48 + o4);
                    float4 y2 = ldcg4(Ys + 96 + o4),  y3 = ldcg4(Ys + 144 + o4);
                    float4 y4 = ldcg4(Ys + 192 + o4);
                    float4 v;
                    v.x = y4.x + a.x*y0.x + a.y*y1.x + a.z*y2.x + a.w*y3.x;
                    v.y = y4.y + a.x*y0.y + a.y*y1.y + a.z*y2.y + a.w*y3.y;
                    v.z = y4.z + a.x*y0.z + a.y*y1.z + a.z*y2.z + a.w*y3.z;
                    v.w = y4.w + a.x*y0.w + a.y*y1.w + a.z*y2.w + a.w*y3.w;
                    float* hp = hout + (size_t)d*HID + o4*4;
                    atomicAdd(hp+0, v.x); atomicAdd(hp+1, v.y);
                    atomicAdd(hp+2, v.z); atomicAdd(hp+3, v.w);
                }
            }
        } else if (L < NL - 1) {
            int li = t - 384;
            const float* Bm = g_B[L + 1];
            #pragma unroll 4
            for (int i = 0; i < 48; i++) {
                int f = li + 128*i;
                int tile = f / 3072, r = f - tile*3072;
                int kk = r >> 4, w4 = r & 15;
                int nj = tile ? (njA + 9) : njA;
                float4 v = __ldg((const float4*)(Bm + kk*NAUG + nj*64 + w4*4));
                *(float4*)((tile ? sB1 : sB0) + kk*64 + w4*4) = v;
            }
        }
        gbar(144u*(3 + 2*L));
    }

    // ---- phase: final LN + head (warp per row; h final = g_h0) ----
    {
        int w = t >> 5, l = t & 31;
        if (w < 8) {
            int r = b + 144*w;
            if (r < NN) {
                float v[6];
                #pragma unroll
                for (int j = 0; j < 6; j++) v[j] = __ldcg(g_h0 + r*HID + l + 32*j);
                float s = ((v[0]+v[1])+(v[2]+v[3]))+(v[4]+v[5]);
                float q = v[0]*v[0]+v[1]*v[1]+v[2]*v[2]+v[3]*v[3]+v[4]*v[4]+v[5]*v[5];
                #pragma unroll
                for (int o = 16; o > 0; o >>= 1) {
                    s += __shfl_xor_sync(0xffffffffu, s, o);
                    q += __shfl_xor_sync(0xffffffffu, q, o);
                }
                float mu = s * (1.f/192.f);
                float rs = rsqrtf(q*(1.f/192.f) - mu*mu + 1e-5f);
                float p0 = 0.f, p1 = 0.f;
                #pragma unroll
                for (int j = 0; j < 6; j++) {
                    int c = l + 32*j;
                    float z = fmaxf(0.f, (v[j] - mu)*rs*__ldg(lng + c) + __ldg(lnb + c));
                    p0 += z * __ldg(ow + c*2);
                    p1 += z * __ldg(ow + c*2 + 1);
                }
                #pragma unroll
                for (int o = 16; o > 0; o >>= 1) {
                    p0 += __shfl_xor_sync(0xffffffffu, p0, o);
                    p1 += __shfl_xor_sync(0xffffffffu, p1, o);
                }
                if (l == 0) {
                    out[r*2]     = p0 + __ldg(ob);
                    out[r*2 + 1] = p1 + __ldg(ob + 1);
                }
            }
        }
    }
}

// ---------------- launcher ----------------
extern "C" void kernel_launch(void* const* d_in, const int* in_sizes, int n_in,
                              void* d_out, int out_size) {
    const float* x       = (const float*)d_in[0];
    const int*   ei      = (const int*)  d_in[1];
    const float* attr    = (const float*)d_in[2];
    const float* cheb_w  = (const float*)d_in[4];
    const float* cheb_b  = (const float*)d_in[5];
    const float* eenc_w  = (const float*)d_in[6];
    const float* eenc_b  = (const float*)d_in[7];
    const float* nn1_w   = (const float*)d_in[8];
    const float* nn1_b   = (const float*)d_in[9];
    const float* nn2_w   = (const float*)d_in[10];
    const float* nn2_b   = (const float*)d_in[11];
    const float* root_w  = (const float*)d_in[12];
    const float* conv_b  = (const float*)d_in[13];
    const float* ln_g    = (const float*)d_in[14];
    const float* ln_b    = (const float*)d_in[15];
    const float* out_w   = (const float*)d_in[16];
    const float* out_b   = (const float*)d_in[17];
    float* out = (float*)d_out;

    cudaFuncSetAttribute(k_M,    cudaFuncAttributeMaxDynamicSharedMemorySize, SMEM_CHEB);
    cudaFuncSetAttribute(k_main, cudaFuncAttributeMaxDynamicSharedMemorySize, SMEM_MAIN);

    // launch 1: Mstack + cheb prep + barrier reset
    k_M<<<dim3(37, NL), 256, SMEM_CHEB>>>(nn2_w, nn2_b, eenc_w, eenc_b,
                                          nn1_w, nn1_b, root_w, ei, x);
    // launch 2: everything else, persistent with software grid barriers
    k_main<<<144, 512, SMEM_MAIN>>>(x, ei, attr, cheb_w, cheb_b, conv_b,
                                    ln_g, ln_b, out_w, out_b, out);
}

// round 16
// speedup vs baseline: 1.2752x; 1.2752x over previous
#include <cuda_runtime.h>

#define NN 1024
#define EE 2048
#define HID 192
#define KCH 5
#define NL 4
#define NAUG 1152
#define MM (HID*HID)          // 36864
#define RSA 68
#define SMEM_MAIN ((192*RSA + 2*192*64)*4)         // 150528 (>= cheb 86016)

typedef unsigned long long ull;

// ---------------- device scratch (allocation-free) ----------------
__device__ float g_S[4*NN*4];
__device__ float g_h0[NN*HID];
__device__ float g_h1[NN*HID];
__device__ float g_Y[NN*NAUG];
__device__ float g_B[NL][HID*NAUG];   // [layer][k][n] fp32
__device__ unsigned g_bar;

// ---------------- helpers ----------------
__device__ __forceinline__ void fma2(ull &c, ull a, ull b) {
    asm("fma.rn.f32x2 %0, %1, %2, %0;" : "+l"(c) : "l"(a), "l"(b));
}
__device__ __forceinline__ ull pk2(float a) {
    ull r; asm("mov.b64 %0, {%1, %1};" : "=l"(r) : "f"(a)); return r;
}
__device__ __forceinline__ float2 up2(ull a) {
    float2 f; asm("mov.b64 {%0, %1}, %2;" : "=f"(f.x), "=f"(f.y) : "l"(a)); return f;
}
__device__ __forceinline__ float4 ldcg4(const float4* p) { return __ldcg(p); }
__device__ __forceinline__ void gbar(unsigned target) {
    __threadfence();
    __syncthreads();
    if (threadIdx.x == 0) {
        atomicAdd(&g_bar, 1u);
        while (*((volatile unsigned*)&g_bar) < target) __nanosleep(32);
    }
    __syncthreads();
}

// ---------------- single persistent kernel ----------------
__global__ void __launch_bounds__(512, 1)
k_all(const float* __restrict__ x, const int* __restrict__ ei,
      const float* __restrict__ attr,
      const float* __restrict__ cw, const float* __restrict__ cbb,
      const float* __restrict__ conv_b,
      const float* __restrict__ lng, const float* __restrict__ lnb,
      const float* __restrict__ ow, const float* __restrict__ ob,
      const float* __restrict__ eenc_w, const float* __restrict__ eenc_b,
      const float* __restrict__ nn1_w,  const float* __restrict__ nn1_b,
      const float* __restrict__ nn2_w,  const float* __restrict__ nn2_b,
      const float* __restrict__ root_w,
      float* __restrict__ out) {
    extern __shared__ float sm[];
    float* sA  = sm;                 // [192][RSA] non-dup, [k][m]
    float* sB0 = sm + 192*RSA;       // [192][64]
    float* sB1 = sB0 + 192*64;
    __shared__ float2 sG[5*HID];
    int t = threadIdx.x, b = blockIdx.x;
    int m0  = (b & 15) * 64;
    int njA = b >> 4;                // 0..8 ; partner n-tile njA+9

    // ================= phase 0: cheb prep (block 0) + Mstack (all blocks) =================
    if (b == 0) {
        // cheb prep in dynamic smem (512 threads)
        float* sdeg = sm;                 // [1024]
        float* sS   = sm + 1024;          // [4][1024][4]
        float* sX   = sm + 1024 + 16384;  // [1024][4]
        #pragma unroll
        for (int i = 0; i < 2; i++) sdeg[t + 512*i] = 0.f;
        #pragma unroll
        for (int i = 0; i < 32; i++) sS[t + 512*i] = 0.f;
        #pragma unroll
        for (int i = 0; i < 8; i++) sX[t + 512*i] = x[t + 512*i];
        __syncthreads();
        int s[4], d[4]; float w[4];
        #pragma unroll
        for (int j = 0; j < 4; j++) {
            int e = t*4 + j;
            s[j] = ei[e]; d[j] = ei[EE + e];
            atomicAdd(&sdeg[s[j]], 1.f);
        }
        __syncthreads();
        float dv[2];
        #pragma unroll
        for (int i = 0; i < 2; i++) dv[i] = sdeg[t + 512*i];
        __syncthreads();
        #pragma unroll
        for (int i = 0; i < 2; i++) sdeg[t + 512*i] = dv[i] > 0.f ? rsqrtf(dv[i]) : 0.f;
        __syncthreads();
        #pragma unroll
        for (int j = 0; j < 4; j++) w[j] = -sdeg[s[j]] * sdeg[d[j]];
        #pragma unroll
        for (int j = 0; j < 4; j++)
            #pragma unroll
            for (int c = 0; c < 4; c++)
                atomicAdd(&sS[d[j]*4 + c], w[j] * sX[s[j]*4 + c]);
        __syncthreads();
        #pragma unroll
        for (int j = 0; j < 4; j++)
            #pragma unroll
            for (int c = 0; c < 4; c++)
                atomicAdd(&sS[4096 + d[j]*4 + c], w[j] * sS[s[j]*4 + c]);
        __syncthreads();
        #pragma unroll
        for (int j = 0; j < 4; j++)
            #pragma unroll
            for (int c = 0; c < 4; c++)
                atomicAdd(&sS[8192 + d[j]*4 + c],
                          w[j] * (2.f*sS[4096 + s[j]*4 + c] - sX[s[j]*4 + c]));
        __syncthreads();
        #pragma unroll
        for (int j = 0; j < 4; j++)
            #pragma unroll
            for (int c = 0; c < 4; c++)
                atomicAdd(&sS[12288 + d[j]*4 + c],
                          w[j] * (2.f*sS[8192 + s[j]*4 + c] - sS[s[j]*4 + c]));
        __syncthreads();
        #pragma unroll
        for (int i = 0; i < 32; i++) g_S[t + 512*i] = sS[t + 512*i];
        __syncthreads();
    }
    // ---- Mstack: layer = b&3, slice = b>>2 (0..35); 2 threads per m4 ----
    {
        int layer = b & 3, slice = b >> 2;
        // G into sG (threads 0..191)
        if (t < HID) {
            float acc5[5] = {0.f, 0.f, 0.f, 0.f, 0.f};
            const float* W1 = nn1_w + layer*MM;
            for (int jb = 0; jb < HID; jb += 8) {
                float wv[8];
                #pragma unroll
                for (int u = 0; u < 8; u++) wv[u] = __ldg(W1 + (jb + u)*HID + t);
                #pragma unroll
                for (int u = 0; u < 8; u++) {
                    int j0 = jb + u;
                    acc5[0] += eenc_w[j0]*wv[u];
                    acc5[1] += eenc_w[HID + j0]*wv[u];
                    acc5[2] += eenc_w[2*HID + j0]*wv[u];
                    acc5[3] += eenc_w[3*HID + j0]*wv[u];
                    acc5[4] += eenc_b[j0]*wv[u];
                }
            }
            acc5[4] += nn1_b[layer*HID + t];
            #pragma unroll
            for (int k = 0; k < 5; k++) sG[k*HID + t] = make_float2(acc5[k], acc5[k]);
        }
        // root copy (threads 0..255)
        if (t < 256) {
            int m = slice*1024 + t*4;
            int j = m / HID, o = m - j*HID;
            float4 v = __ldg((const float4*)(root_w + (size_t)layer*MM + m));
            *(float4*)(g_B[layer] + j*NAUG + 5*HID + o) = v;
        }
        __syncthreads();

        int m4 = (slice*256 + (t >> 1)) * 4;
        int jh = t & 1;
        const float* W = nn2_w + (size_t)layer * HID * MM;
        ull acc[5][2] = {};
        for (int jb = jh*96; jb < jh*96 + 96; jb += 8) {
            float4 vv[8];
            #pragma unroll
            for (int u = 0; u < 8; u++)
                vv[u] = __ldg((const float4*)(W + (size_t)(jb + u)*MM + m4));
            #pragma unroll
            for (int u = 0; u < 8; u++) {
                int j = jb + u;
                ull v01, v23;
                asm("mov.b64 %0, {%1, %2};" : "=l"(v01) : "f"(vv[u].x), "f"(vv[u].y));
                asm("mov.b64 %0, {%1, %2};" : "=l"(v23) : "f"(vv[u].z), "f"(vv[u].w));
                #pragma unroll
                for (int k = 0; k < 5; k++) {
                    ull gk = *(const ull*)&sG[k*HID + j];
                    fma2(acc[k][0], gk, v01);
                    fma2(acc[k][1], gk, v23);
                }
            }
        }
        // partner reduce (lanes differ by 1) + writeout on jh==0
        float2 r[5][2];
        #pragma unroll
        for (int k = 0; k < 5; k++)
            #pragma unroll
            for (int h = 0; h < 2; h++) {
                ull other = __shfl_xor_sync(0xffffffffu, acc[k][h], 1);
                float2 a = up2(acc[k][h]), bo = up2(other);
                r[k][h] = make_float2(a.x + bo.x, a.y + bo.y);
            }
        if (jh == 0) {
            float4 bv = __ldg((const float4*)(nn2_b + (size_t)(b & 3)*MM + m4));
            r[4][0].x += bv.x; r[4][0].y += bv.y;
            r[4][1].x += bv.z; r[4][1].y += bv.w;
            int j2 = m4 / HID;
            int o  = m4 - j2 * HID;
            float* dst = g_B[b & 3] + j2*NAUG + o;
            #pragma unroll
            for (int k = 0; k < 5; k++) {
                *(float2*)(dst + k*HID)     = r[k][0];
                *(float2*)(dst + k*HID + 2) = r[k][1];
            }
        }
    }
    gbar(144u);

    // ================= phase 1: cheb_out (t<384) + B-prefetch layer0 (t>=384) =================
    if (t < 384) {
        int g = t / 192, o = t - g*192;
        for (int i = 0; i < 4; i++) {
            int r = b*2 + g + 288*i;
            if (r < NN) {
                float acc = __ldg(cbb + o);
                #pragma unroll
                for (int c = 0; c < 4; c++) {
                    float xv = __ldg(x + r*4 + c);
                    float s1 = g_S[r*4+c],        s2 = g_S[4096 + r*4+c];
                    float s3 = g_S[8192 + r*4+c], s4 = g_S[12288 + r*4+c];
                    float t2 = 2.f*s2 - xv, t3 = 2.f*s3 - s1, t4 = 2.f*s4 - 2.f*s2 + xv;
                    acc += xv*__ldg(cw + c*HID + o)
                         + s1*__ldg(cw + (4+c)*HID + o)
                         + t2*__ldg(cw + (8+c)*HID + o)
                         + t3*__ldg(cw + (12+c)*HID + o)
                         + t4*__ldg(cw + (16+c)*HID + o);
                }
                g_h0[r*HID + o] = acc;
            }
        }
    } else {
        int li = t - 384;
        const float* Bm = g_B[0];
        #pragma unroll 4
        for (int i = 0; i < 48; i++) {
            int f = li + 128*i;
            int tile = f / 3072, r = f - tile*3072;
            int kk = r >> 4, w4 = r & 15;
            int nj = tile ? (njA + 9) : njA;
            float4 v = __ldcg((const float4*)(Bm + kk*NAUG + nj*64 + w4*4));
            *(float4*)((tile ? sB1 : sB0) + kk*64 + w4*4) = v;
        }
    }
    gbar(288u);

    // ================= layers =================
    for (int L = 0; L < NL; L++) {
        const float* hin  = (L & 1) ? g_h1 : g_h0;
        float*       hout = (L & 1) ? g_h0 : g_h1;
        int do_ln = (L > 0);

        // ---- A prologue: 64 rows x 4 threads/row (t < 256), LN in registers ----
        if (t < 256) {
            int m = t >> 2, q = t & 3;
            const float4* rp = (const float4*)(hin + (size_t)(m0 + m)*HID) + q*12;
            float4 v[12];
            #pragma unroll
            for (int i = 0; i < 12; i++) v[i] = ldcg4(rp + i);
            float mu = 0.f, rs = 0.f;
            if (do_ln) {
                float s = 0.f, qq = 0.f;
                #pragma unroll
                for (int i = 0; i < 12; i++) {
                    s  += (v[i].x + v[i].y) + (v[i].z + v[i].w);
                    qq += v[i].x*v[i].x + v[i].y*v[i].y + v[i].z*v[i].z + v[i].w*v[i].w;
                }
                s  += __shfl_xor_sync(0xffffffffu, s, 1);
                s  += __shfl_xor_sync(0xffffffffu, s, 2);
                qq += __shfl_xor_sync(0xffffffffu, qq, 1);
                qq += __shfl_xor_sync(0xffffffffu, qq, 2);
                mu = s * (1.f/192.f);
                rs = rsqrtf(qq*(1.f/192.f) - mu*mu + 1e-5f);
            }
            #pragma unroll
            for (int i = 0; i < 12; i++) {
                int k = q*48 + i*4;
                float vv[4] = {v[i].x, v[i].y, v[i].z, v[i].w};
                #pragma unroll
                for (int e = 0; e < 4; e++) {
                    float z = vv[e];
                    if (do_ln)
                        z = fmaxf(0.f, (z - mu)*rs*__ldg(lng + L*HID + k + e)
                                        + __ldg(lnb + L*HID + k + e));
                    sA[(k + e)*RSA + m] = z;
                }
            }
        }
        __syncthreads();

        // ---- GEMM main: warp-uniform A broadcast; lane = 8m x 2n ----
        {
            int half = t >> 8, th = t & 255;
            int w = th >> 5, lane = th & 31;       // warp m-offset 8*w
            const float* sB = half ? sB1 : sB0;
            int nj = half ? (njA + 9) : njA;
            const float* aBase = sA + 8*w;
            const float* bBase = sB + 2*lane;
            ull acc[8] = {};
            #pragma unroll 4
            for (int kk = 0; kk < 192; kk++) {
                float4 a0 = *(const float4*)(aBase + kk*RSA);
                float4 a1 = *(const float4*)(aBase + kk*RSA + 4);
                ull bp = *(const ull*)(bBase + kk*64);
                fma2(acc[0], pk2(a0.x), bp);
                fma2(acc[1], pk2(a0.y), bp);
                fma2(acc[2], pk2(a0.z), bp);
                fma2(acc[3], pk2(a0.w), bp);
                fma2(acc[4], pk2(a1.x), bp);
                fma2(acc[5], pk2(a1.y), bp);
                fma2(acc[6], pk2(a1.z), bp);
                fma2(acc[7], pk2(a1.w), bp);
            }
            int n0 = nj*64;
            int nc = 2*lane;
            if (nj < 15) {
                #pragma unroll
                for (int i = 0; i < 8; i++)
                    *(float2*)(g_Y + (size_t)(m0 + 8*w + i)*NAUG + n0 + nc) = up2(acc[i]);
            } else {
                int ob2 = n0 - 960 + nc;
                float2 cbv = *(const float2*)(conv_b + L*HID + ob2);
                #pragma unroll
                for (int i = 0; i < 8; i++) {
                    int row = m0 + 8*w + i;
                    float2 r = up2(acc[i]);
                    r.x += cbv.x; r.y += cbv.y;
                    if (do_ln) {
                        float2 hv = __ldcg((const float2*)(hin + (size_t)row*HID + ob2));
                        r.x += hv.x; r.y += hv.y;
                    }
                    *(float2*)(hout + (size_t)row*HID + ob2) = r;
                }
            }
        }
        gbar(144u*(3 + 2*L));

        // ---- escatter (t<384) + B-prefetch layer L+1 (t>=384) ----
        if (t < 384) {
            int g = t / 48, o4 = t - g*48;
            #pragma unroll
            for (int i = 0; i < 2; i++) {
                int e = b*8 + g + 1152*i;
                if (e < EE) {
                    int s = __ldg(ei + e), d = __ldg(ei + EE + e);
                    float4 a = __ldg((const float4*)(attr + e*4));
                    const float4* Ys = (const float4*)(g_Y + (size_t)s*NAUG);
                    float4 y0 = ldcg4(Ys + o4),       y1 = ldcg4(Ys + 48 + o4);
                    float4 y2 = ldcg4(Ys + 96 + o4),  y3 = ldcg4(Ys + 144 + o4);
                    float4 y4 = ldcg4(Ys + 192 + o4);
                    float4 v;
                    v.x = y4.x + a.x*y0.x + a.y*y1.x + a.z*y2.x + a.w*y3.x;
                    v.y = y4.y + a.x*y0.y + a.y*y1.y + a.z*y2.y + a.w*y3.y;
                    v.z = y4.z + a.x*y0.z + a.y*y1.z + a.z*y2.z + a.w*y3.z;
                    v.w = y4.w + a.x*y0.w + a.y*y1.w + a.z*y2.w + a.w*y3.w;
                    float* hp = hout + (size_t)d*HID + o4*4;
                    atomicAdd(hp+0, v.x); atomicAdd(hp+1, v.y);
                    atomicAdd(hp+2, v.z); atomicAdd(hp+3, v.w);
                }
            }
        } else if (L < NL - 1) {
            int li = t - 384;
            const float* Bm = g_B[L + 1];
            #pragma unroll 4
            for (int i = 0; i < 48; i++) {
                int f = li + 128*i;
                int tile = f / 3072, r = f - tile*3072;
                int kk = r >> 4, w4 = r & 15;
                int nj = tile ? (njA + 9) : njA;
                float4 v = __ldcg((const float4*)(Bm + kk*NAUG + nj*64 + w4*4));
                *(float4*)((tile ? sB1 : sB0) + kk*64 + w4*4) = v;
            }
        }
        gbar(144u*(4 + 2*L));
    }

    // ================= final LN + head (warp per row; h final = g_h0) =================
    {
        int w = t >> 5, l = t & 31;
        if (w < 8) {
            int r = b + 144*w;
            if (r < NN) {
                float v[6];
                #pragma unroll
                for (int j = 0; j < 6; j++) v[j] = __ldcg(g_h0 + r*HID + l + 32*j);
                float s = ((v[0]+v[1])+(v[2]+v[3]))+(v[4]+v[5]);
                float q = v[0]*v[0]+v[1]*v[1]+v[2]*v[2]+v[3]*v[3]+v[4]*v[4]+v[5]*v[5];
                #pragma unroll
                for (int o = 16; o > 0; o >>= 1) {
                    s += __shfl_xor_sync(0xffffffffu, s, o);
                    q += __shfl_xor_sync(0xffffffffu, q, o);
                }
                float mu = s * (1.f/192.f);
                float rs = rsqrtf(q*(1.f/192.f) - mu*mu + 1e-5f);
                float p0 = 0.f, p1 = 0.f;
                #pragma unroll
                for (int j = 0; j < 6; j++) {
                    int c = l + 32*j;
                    float z = fmaxf(0.f, (v[j] - mu)*rs*__ldg(lng + c) + __ldg(lnb + c));
                    p0 += z * __ldg(ow + c*2);
                    p1 += z * __ldg(ow + c*2 + 1);
                }
                #pragma unroll
                for (int o = 16; o > 0; o >>= 1) {
                    p0 += __shfl_xor_sync(0xffffffffu, p0, o);
                    p1 += __shfl_xor_sync(0xffffffffu, p1, o);
                }
                if (l == 0) {
                    out[r*2]     = p0 + __ldg(ob);
                    out[r*2 + 1] = p1 + __ldg(ob + 1);
                }
            }
        }
    }

    // ---- safe barrier reset for graph replay: arrive-only, block 0 resets ----
    __syncthreads();
    if (t == 0) {
        atomicAdd(&g_bar, 1u);
        if (b == 0) {
            while (*((volatile unsigned*)&g_bar) < 1584u) __nanosleep(32);
            atomicExch(&g_bar, 0u);
        }
    }
}

// ---------------- launcher ----------------
extern "C" void kernel_launch(void* const* d_in, const int* in_sizes, int n_in,
                              void* d_out, int out_size) {
    const float* x       = (const float*)d_in[0];
    const int*   ei      = (const int*)  d_in[1];
    const float* attr    = (const float*)d_in[2];
    const float* cheb_w  = (const float*)d_in[4];
    const float* cheb_b  = (const float*)d_in[5];
    const float* eenc_w  = (const float*)d_in[6];
    const float* eenc_b  = (const float*)d_in[7];
    const float* nn1_w   = (const float*)d_in[8];
    const float* nn1_b   = (const float*)d_in[9];
    const float* nn2_w   = (const float*)d_in[10];
    const float* nn2_b   = (const float*)d_in[11];
    const float* root_w  = (const float*)d_in[12];
    const float* conv_b  = (const float*)d_in[13];
    const float* ln_g    = (const float*)d_in[14];
    const float* ln_b    = (const float*)d_in[15];
    const float* out_w   = (const float*)d_in[16];
    const float* out_b   = (const float*)d_in[17];
    float* out = (float*)d_out;

    cudaFuncSetAttribute(k_all, cudaFuncAttributeMaxDynamicSharedMemorySize, SMEM_MAIN);

    // ONE launch: Mstack + cheb + 4 layers + head, persistent with grid barriers
    k_all<<<144, 512, SMEM_MAIN>>>(x, ei, attr, cheb_w, cheb_b, conv_b,
                                   ln_g, ln_b, out_w, out_b,
                                   eenc_w, eenc_b, nn1_w, nn1_b, nn2_w, nn2_b,
                                   root_w, out);
}